// round 5
// baseline (speedup 1.0000x reference)
#include <cuda_runtime.h>
#include <math.h>

#define N_MAX   196608
#define TILE    96
#define TMAX    2048
#define MAXDET  100
#define CAP     2048
#define SPAN    448u          // candidate window below max, in ordered-ulp units
#define LOU     0xBC23D70Au   // ordf(0.01f)
#define NMS_T   512

__device__ float              g_scores[N_MAX];
__device__ float4             g_boxes[N_MAX];
__device__ unsigned           g_maxu;     // zero-init; reset by nms each replay
__device__ int                g_count;    // reset by nms each replay
__device__ unsigned long long g_candKey[CAP];

__device__ __forceinline__ unsigned ordf(float f) {
    unsigned u = __float_as_uint(f);
    return (u & 0x80000000u) ? ~u : (u | 0x80000000u);
}
__device__ __forceinline__ float unordf(unsigned u) {
    return __uint_as_float((u & 0x80000000u) ? (u ^ 0x80000000u) : ~u);
}
__device__ __forceinline__ float read_dim(const void* p) {
    int iv = *(const int*)p;
    if (iv >= 1 && iv <= (1 << 20)) return (float)iv;
    float fv = *(const float*)p;
    if (fv >= 1.0f && fv <= 1048576.0f) return fv;
    double dv = *(const double*)p;
    if (dv >= 1.0 && dv <= 1048576.0) return (float)dv;
    long long lv = *(const long long*)p;
    return (float)lv;
}
__device__ __forceinline__ bool iou_gt_half(float4 A, float4 B) {
    float x1 = fmaxf(A.x, B.x), y1 = fmaxf(A.y, B.y);
    float x2 = fminf(A.z, B.z), y2 = fminf(A.w, B.w);
    float inter = fmaxf(x2 - x1, 0.0f) * fmaxf(y2 - y1, 0.0f);
    float a1 = (A.z - A.x) * (A.w - A.y);
    float a2 = (B.z - B.x) * (B.w - B.y);
    float iou = inter / (a1 + a2 - inter + 1e-8f);
    return iou > 0.5f;
}

__device__ __forceinline__ void decode_box(int i, unsigned u,
                                           const float* __restrict__ reg,
                                           const float* __restrict__ anc,
                                           float imh, float imw) {
    float best = unordf(u);
    float4 a = ((const float4*)anc)[i];
    float4 r = ((const float4*)reg)[i];
    float wa  = a.z - a.x;
    float ha  = a.w - a.y;
    float cxa = a.x + 0.5f * wa;
    float cya = a.y + 0.5f * ha;
    float cx  = cxa + r.x * 0.1f * wa;
    float cy  = cya + r.y * 0.1f * ha;
    float w   = expf(r.z * 0.2f) * wa;
    float h   = expf(r.w * 0.2f) * ha;
    float4 b;
    b.x = fminf(fmaxf(cx - 0.5f * w, 0.0f), imw);
    b.y = fminf(fmaxf(cy - 0.5f * h, 0.0f), imh);
    b.z = fminf(fmaxf(cx + 0.5f * w, 0.0f), imw);
    b.w = fminf(fmaxf(cy + 0.5f * h, 0.0f), imh);
    g_boxes[i]  = b;
    g_scores[i] = (best > 0.01f) ? best : -INFINITY;
}

// ---------------------------------------------------------------------------
// Kernel 1 (C==90 fast path): 8 threads per anchor-pair, register max over
// 45 coalesced float4s, 3-shuffle group reduce, zero atomics.
// ---------------------------------------------------------------------------
__global__ void decode90_kernel(const float* __restrict__ cls,
                                const float* __restrict__ reg,
                                const float* __restrict__ anc,
                                const void* ph, const void* pw,
                                int N) {
    const unsigned FULL = 0xffffffffu;
    int tid  = threadIdx.x;
    int sub  = tid & 7;
    int P    = blockIdx.x * 32 + (tid >> 3);
    int pairs = N >> 1;

    unsigned mA = 0u, mB = 0u;
    if (P < pairs) {
        const float4* src = (const float4*)cls + (long long)P * 45;
        #pragma unroll
        for (int it = 0; it < 6; it++) {
            int q = sub + it * 8;
            if (q < 45) {
                float4 v = src[q];
                if (q < 22) {
                    mA = max(mA, ordf(fmaxf(fmaxf(v.x, v.y), fmaxf(v.z, v.w))));
                } else if (q == 22) {   // floats 88..91: x,y -> A; z,w -> B
                    mA = max(mA, ordf(fmaxf(v.x, v.y)));
                    mB = max(mB, ordf(fmaxf(v.z, v.w)));
                } else {
                    mB = max(mB, ordf(fmaxf(fmaxf(v.x, v.y), fmaxf(v.z, v.w))));
                }
            }
        }
    }
    // reduce across the 8-lane group (xor offsets stay in-group)
    #pragma unroll
    for (int off = 1; off <= 4; off <<= 1) {
        mA = max(mA, __shfl_xor_sync(FULL, mA, off));
        mB = max(mB, __shfl_xor_sync(FULL, mB, off));
    }

    if (P < pairs && sub < 2) {
        float imw = read_dim(pw);
        float imh = read_dim(ph);
        decode_box(2 * P + sub, sub == 0 ? mA : mB, reg, anc, imh, imw);
    }

    // odd-N tail anchor: serial handling by one thread
    if ((N & 1) && blockIdx.x == 0 && tid == 0) {
        const float* row = cls + (long long)(N - 1) * 90;
        unsigned u = 0u;
        for (int j = 0; j < 90; j++) u = max(u, ordf(row[j]));
        float imw = read_dim(pw);
        float imh = read_dim(ph);
        decode_box(N - 1, u, reg, anc, imh, imw);
        atomicMax(&g_maxu, u);
    }

    // warp max -> one global atomic per warp
    unsigned wm = max(mA, mB);
    #pragma unroll
    for (int off = 8; off <= 16; off <<= 1)
        wm = max(wm, __shfl_xor_sync(FULL, wm, off));
    if ((tid & 31) == 0) atomicMax(&g_maxu, wm);
}

// Generic-C path: warp per anchor (correct for any C).
__global__ void decodegen_kernel(const float* __restrict__ cls,
                                 const float* __restrict__ reg,
                                 const float* __restrict__ anc,
                                 const void* ph, const void* pw,
                                 int N, int C) {
    const unsigned FULL = 0xffffffffu;
    int warp = (blockIdx.x * blockDim.x + threadIdx.x) >> 5;
    int lane = threadIdx.x & 31;
    if (warp >= N) return;
    const float* row = cls + (long long)warp * C;
    unsigned u = 0u;
    for (int j = lane; j < C; j += 32) u = max(u, ordf(row[j]));
    #pragma unroll
    for (int off = 16; off; off >>= 1)
        u = max(u, __shfl_xor_sync(FULL, u, off));
    if (lane == 0) {
        float imw = read_dim(pw);
        float imh = read_dim(ph);
        decode_box(warp, u, reg, anc, imh, imw);
        atomicMax(&g_maxu, u);
    }
}

// ---------------------------------------------------------------------------
// Kernel 2: compact candidates with u >= maxu - SPAN (and > threshold).
// ---------------------------------------------------------------------------
__global__ void compact_kernel(int N) {
    int gid = blockIdx.x * blockDim.x + threadIdx.x;
    if (gid >= N) return;
    unsigned u = ordf(g_scores[gid]);
    unsigned maxu = g_maxu;
    unsigned cut = (maxu > LOU + 1u + SPAN) ? (maxu - SPAN) : (LOU + 1u);
    if (u > LOU && u >= cut) {
        int pos = atomicAdd(&g_count, 1);
        if (pos < CAP)
            g_candKey[pos] = ((unsigned long long)u << 32) | (unsigned)(~gid);
    }
}

// ---------------------------------------------------------------------------
// Kernel 3: single block. Bitonic sort (desc), mask-based warp-batched greedy
// NMS (exact reference semantics), class argmax of winners, output.
// Exact fallback retained for adversarial distributions / overflow.
// ---------------------------------------------------------------------------
__global__ void nms_kernel(float* __restrict__ out,
                           const float* __restrict__ cls,
                           int N, int C) {
    __shared__ unsigned long long sKeys[TMAX];
    __shared__ float4 sSelBox[MAXDET];
    __shared__ int    sSelIdx[MAXDET];
    __shared__ float  sSelScore[MAXDET];
    __shared__ float4 sBatch[32];
    __shared__ int    sNsel, sSup, sTotal;
    __shared__ unsigned sCut;
    __shared__ float4 sBx;
    __shared__ unsigned long long sWarp[16];
    __shared__ unsigned long long sTileP[3];

    int tid  = threadIdx.x;
    int wid  = tid >> 5;
    int lane = tid & 31;
    const unsigned FULL = 0xffffffffu;

    if (tid == 0) {
        sNsel  = 0;
        sTotal = g_count;
        unsigned maxu = g_maxu;
        sCut = (maxu > LOU + 1u + SPAN) ? (maxu - SPAN) : (LOU + 1u);
        g_count = 0;        // reset for next graph replay
        g_maxu  = 0u;
    }
    __syncthreads();

    int total    = sTotal;
    unsigned cutU = sCut;
    bool ovf = total > CAP;
    int cnt  = ovf ? 0 : total;

    int M = 1; while (M < cnt) M <<= 1;
    if (M < 2) M = 2;

    for (int k = tid; k < M; k += NMS_T)
        sKeys[k] = (k < cnt) ? g_candKey[k] : 0ull;
    __syncthreads();

    // ---- bitonic sort, descending ----
    if (cnt > 1) {
        for (int k2 = 2; k2 <= M; k2 <<= 1) {
            for (int j = k2 >> 1; j > 0; j >>= 1) {
                for (int i = tid; i < M; i += NMS_T) {
                    int l = i ^ j;
                    if (l > i) {
                        unsigned long long a = sKeys[i], b = sKeys[l];
                        bool desc = ((i & k2) == 0);
                        if (desc ? (a < b) : (a > b)) { sKeys[i] = b; sKeys[l] = a; }
                    }
                }
                __syncthreads();
            }
        }
    }

    // ---- warp-batched greedy NMS with suppression bitmasks (warp 0) ----
    if (tid < 32) {
        int nsel = 0;
        for (int bse = 0; bse < cnt && nsel < MAXDET; bse += 32) {
            int p = bse + tid;
            bool valid = p < cnt;
            unsigned long long key = valid ? sKeys[p] : 0ull;
            unsigned hi = (unsigned)(key >> 32);
            int   idx = (int)(~(unsigned)(key & 0xffffffffu));
            float sc  = unordf(hi);
            bool alive = valid && hi > 0x007FFFFFu;
            float4 b = alive ? g_boxes[idx]
                             : make_float4(-1e30f, -1e30f, -1e30f, -1e30f);
            sBatch[tid] = b;
            __syncwarp();

            for (int j = 0; j < nsel; j++)
                if (alive && iou_gt_half(b, sSelBox[j])) alive = false;

            unsigned supmask = 0;
            #pragma unroll 4
            for (int j = 0; j < 32; j++)
                supmask |= ((unsigned)iou_gt_half(b, sBatch[j])) << j;

            unsigned am = __ballot_sync(FULL, alive);
            unsigned selM = 0;
            while (am && nsel < MAXDET) {
                int l = __ffs(am) - 1;
                selM |= 1u << l;
                nsel++;
                if (tid == l) alive = false;
                else if (tid > l && ((supmask >> l) & 1u)) alive = false;
                am = __ballot_sync(FULL, alive);
            }
            int base = nsel - __popc(selM);
            if ((selM >> tid) & 1u) {
                int r = base + __popc(selM & ((1u << tid) - 1u));
                sSelBox[r] = b; sSelIdx[r] = idx; sSelScore[r] = sc;
            }
            __syncwarp();
        }
        if (tid == 0) sNsel = nsel;
    }
    __syncthreads();
    int nsel = sNsel;

    // ---- exact fallback ----
    if (nsel < MAXDET && (ovf || cutU > LOU + 1u)) {
        unsigned tauOrd = ovf ? 0xFFFFFFFFu : cutU;
        int T = (N + TILE - 1) / TILE;
        for (int t = tid; t < TMAX; t += NMS_T) {
            unsigned long long best = 0ull;
            if (t < T) {
                int bb = t * TILE;
                for (int k = 0; k < TILE; k++) {
                    int ii = bb + k;
                    if (ii >= N) break;
                    unsigned u = ordf(g_scores[ii]);
                    if (u >= tauOrd) continue;
                    unsigned long long kk =
                        ((unsigned long long)u << 32) | (unsigned)(~ii);
                    if (kk > best) best = kk;
                }
            }
            sKeys[t] = best;
        }
        __syncthreads();

        while (nsel < MAXDET) {
            unsigned long long best = 0ull;
            #pragma unroll
            for (int k = 0; k < TMAX / NMS_T; k++) {
                unsigned long long v = sKeys[tid + k * NMS_T];
                best = (v > best) ? v : best;
            }
            #pragma unroll
            for (int off = 16; off; off >>= 1) {
                unsigned long long o = __shfl_down_sync(FULL, best, off);
                best = (o > best) ? o : best;
            }
            if (lane == 0) sWarp[wid] = best;
            __syncthreads();
            if (tid < 32) {
                unsigned long long v = (tid < 16) ? sWarp[tid] : 0ull;
                #pragma unroll
                for (int off = 8; off; off >>= 1) {
                    unsigned long long o = __shfl_down_sync(FULL, v, off);
                    v = (o > v) ? o : v;
                }
                if (tid == 0) sWarp[0] = v;
            }
            __syncthreads();
            unsigned long long win = sWarp[0];
            unsigned hi = (unsigned)(win >> 32);
            if (hi <= 0x007FFFFFu) break;
            int   i   = (int)(~(unsigned)(win & 0xffffffffu));
            float val = unordf(hi);
            if (tid == 0) { g_scores[i] = -INFINITY; sBx = g_boxes[i]; sSup = 0; }
            __syncthreads();
            int t = i / TILE;
            if (tid < TILE) {
                int ii = t * TILE + tid;
                unsigned u = (ii < N) ? ordf(g_scores[ii]) : 0x007FFFFFu;
                unsigned long long kk = 0ull;
                if (u < tauOrd)
                    kk = ((unsigned long long)u << 32) | (unsigned)(~ii);
                #pragma unroll
                for (int off = 16; off; off >>= 1) {
                    unsigned long long o = __shfl_down_sync(FULL, kk, off);
                    kk = (o > kk) ? o : kk;
                }
                if (lane == 0) sTileP[wid] = kk;
            }
            if (tid >= 128 && tid < 128 + nsel) {
                if (iou_gt_half(sSelBox[tid - 128], sBx)) sSup = 1;
            }
            __syncthreads();
            if (tid == 0) {
                unsigned long long kk = sTileP[0];
                if (sTileP[1] > kk) kk = sTileP[1];
                if (sTileP[2] > kk) kk = sTileP[2];
                sKeys[t] = kk;
                if (!sSup) {
                    sSelBox[nsel] = sBx; sSelIdx[nsel] = i; sSelScore[nsel] = val;
                    sNsel = nsel + 1;
                }
            }
            __syncthreads();
            nsel = sNsel;
        }
    }
    __syncthreads();
    nsel = sNsel;

    // ---- class argmax for selected rows (warp per row) ----
    for (int r = wid; r < nsel; r += NMS_T / 32) {
        int i = sSelIdx[r];
        const float* row = cls + (long long)i * C;
        float best = -INFINITY;
        int   bidx = 0x7fffffff;
        for (int j = lane; j < C; j += 32) {
            float v = row[j];
            if (v > best) { best = v; bidx = j; }
        }
        #pragma unroll
        for (int off = 16; off; off >>= 1) {
            float ov = __shfl_down_sync(FULL, best, off);
            int   oi = __shfl_down_sync(FULL, bidx, off);
            if (ov > best || (ov == best && oi < bidx)) { best = ov; bidx = oi; }
        }
        if (lane == 0) out[100 + r] = (float)bidx;
    }

    for (int r = tid; r < MAXDET; r += NMS_T) {
        bool k = r < nsel;
        out[r]       = k ? sSelScore[r] : 0.0f;
        out[600 + r] = k ? 1.0f : 0.0f;
        float4 b = k ? sSelBox[r] : make_float4(0.f, 0.f, 0.f, 0.f);
        out[200 + 4 * r + 0] = b.x;
        out[200 + 4 * r + 1] = b.y;
        out[200 + 4 * r + 2] = b.z;
        out[200 + 4 * r + 3] = b.w;
        if (!k) out[100 + r] = -1.0f;
    }
}

extern "C" void kernel_launch(void* const* d_in, const int* in_sizes, int n_in,
                              void* d_out, int out_size) {
    const float* cls = (const float*)d_in[0];
    const float* reg = (const float*)d_in[1];
    const float* anc = (const float*)d_in[2];
    const void*  ph  = d_in[3];
    const void*  pw  = d_in[4];

    int N = in_sizes[2] / 4;
    int C = in_sizes[0] / N;

    if (C == 90) {
        int pairs   = N >> 1;
        int blocksD = (pairs + 31) / 32;   // 32 pairs (64 anchors) per 256-thr block
        decode90_kernel<<<blocksD, 256>>>(cls, reg, anc, ph, pw, N);
    } else {
        int blocksD = (N + 7) / 8;         // warp per anchor
        decodegen_kernel<<<blocksD, 256>>>(cls, reg, anc, ph, pw, N, C);
    }

    int blocksN = (N + 255) / 256;
    compact_kernel<<<blocksN, 256>>>(N);

    nms_kernel<<<1, NMS_T>>>((float*)d_out, cls, N, C);
}